// round 13
// baseline (speedup 1.0000x reference)
#include <cuda_runtime.h>
#include <math.h>

// Problem constants (fixed shapes)
#define B_  4
#define C_  32
#define T_  48
#define N_  2000
#define E_  16000
#define BT_ (B_ * T_)   // 192

#define PTS  128        // points per conv block
#define NBLK 16         // ceil(2000/128)
#define XWSTRIDE 36     // tile row stride (words); 36*4 % 16 == 0 -> STS.128 ok

typedef unsigned long long ull;

// ---------------------------------------------------------------------------
// Scratch (device globals)
// ---------------------------------------------------------------------------
__device__ float g_xw[BT_ * N_ * C_];     // h = relu(conv1), layout [g][n][c]
__device__ float g_gout[BT_ * C_ * N_];   // agg output z, layout [g][c][n]
__device__ int   g_srcb[E_];
__device__ int   g_dstb[E_];
__device__ int   g_off[N_ + 1];
__device__ int   g_csr_src[E_];
__device__ float g_csr_w[E_];
__device__ float g_invdeg[N_];
__device__ float g_w2p[32 * 3 * 32];      // folded w2' : [(c1*3+kt)*32 + co]
__device__ float g_bk[3 * 32];            // per-tap bias : [kt*32 + co]

// ---------------------------------------------------------------------------
// f32x2 helpers
// ---------------------------------------------------------------------------
__device__ __forceinline__ ull dup2(float x) {
    ull r;
    unsigned u = __float_as_uint(x);
    asm("mov.b64 %0, {%1, %1};" : "=l"(r) : "r"(u));
    return r;
}
__device__ __forceinline__ void ffma2(ull& acc, ull a, ull b) {
    asm("fma.rn.f32x2 %0, %1, %2, %0;" : "+l"(acc) : "l"(a), "l"(b));
}
__device__ __forceinline__ float2 unpack2(ull v) {
    unsigned lo, hi;
    asm("mov.b64 {%0, %1}, %2;" : "=r"(lo), "=r"(hi) : "l"(v));
    return make_float2(__uint_as_float(lo), __uint_as_float(hi));
}

// ---------------------------------------------------------------------------
// K1: conv1+relu, 2 temporal outputs per block sharing 4 x-planes.
// Point-packed f32x2: inputs loaded as ulonglong2 (no dup movs), weights
// pre-duplicated in smem (no dup movs). CSR prep + weight folding fused in
// as one extra block (blockIdx.x == NBLK).
// Thread map: cog = tid&7 (co0 = cog*4), ptg = tid>>3 (4 points each).
// acc[tt][pp][c]: f32x2 over point pair (nb+2pp, nb+2pp+1), channel co0+c.
// ---------------------------------------------------------------------------
__global__ void __launch_bounds__(256, 3) k_conv1(
    const float* __restrict__ x,
    const void*  __restrict__ edges,
    const float* __restrict__ w1,
    const float* __restrict__ b1,
    const float* __restrict__ gcn_w,
    const float* __restrict__ gcn_b,
    const float* __restrict__ w2)
{
    __shared__ __align__(16) union U {
        float pool[2 * PTS * XWSTRIDE];   // 2 transpose tiles [128][36]
        struct {
            int   cnt[2000];
            int   off[2000];
            float dinv[2000];
            int   wsum[8];
            int   is64;
        } prep;
    } u;
    __shared__ __align__(16) ull w1d[96 * 32];   // dup'd: [(ci*3+kt)*32 + co]
    __shared__ __align__(16) ull b1d[32];

    int tid = threadIdx.x;

    // ---------------- fused preprocessing block ----------------
    if (blockIdx.x == NBLK) {
        if (blockIdx.y != 0 || blockIdx.z != 0) return;

        if (tid == 0) {
            const int* q = (const int*)edges;
            int ok = 1;
            #pragma unroll 1
            for (int i = 0; i < 64; i++) {
                if (q[2 * i + 1] != 0) { ok = 0; break; }
            }
            u.prep.is64 = ok;
        }
        for (int i = tid; i < N_; i += 256) u.prep.cnt[i] = 0;
        __syncthreads();
        const int is64 = u.prep.is64;

        #pragma unroll 1
        for (int e = tid; e < E_; e += 256) {
            int s, d;
            if (is64) {
                const long long* p = (const long long*)edges;
                s = (int)p[e];
                d = (int)p[E_ + e];
            } else {
                const int* p = (const int*)edges;
                s = p[e];
                d = p[E_ + e];
            }
            g_srcb[e] = s;
            g_dstb[e] = d;
            atomicAdd(&u.prep.cnt[d], 1);
        }
        __syncthreads();

        int lane = tid & 31, wid = tid >> 5;
        int base = tid * 8;
        int c[8];
        int sum = 0;
        #pragma unroll
        for (int i = 0; i < 8; i++) {
            int idx = base + i;
            c[i] = (idx < N_) ? u.prep.cnt[idx] : 0;
            sum += c[i];
        }
        int incl = sum;
        #pragma unroll
        for (int o = 1; o < 32; o <<= 1) {
            int v = __shfl_up_sync(0xffffffffu, incl, o);
            if (lane >= o) incl += v;
        }
        if (lane == 31) u.prep.wsum[wid] = incl;
        __syncthreads();
        int woff = 0;
        #pragma unroll
        for (int w = 0; w < 8; w++) woff += (w < wid) ? u.prep.wsum[w] : 0;
        int run = woff + incl - sum;
        #pragma unroll
        for (int i = 0; i < 8; i++) {
            int idx = base + i;
            if (idx < N_) {
                u.prep.off[idx] = run;
                g_off[idx] = run;
                float deg = (float)c[i] + 1.0f;
                u.prep.dinv[idx] = rsqrtf(deg);
                g_invdeg[idx] = 1.0f / deg;
            }
            run += c[i];
        }
        if (tid == 0) g_off[N_] = E_;
        __syncthreads();
        for (int i = tid; i < N_; i += 256) u.prep.cnt[i] = 0;
        __syncthreads();

        #pragma unroll 1
        for (int e = tid; e < E_; e += 256) {
            int s = g_srcb[e];
            int d = g_dstb[e];
            int pos = atomicAdd(&u.prep.cnt[d], 1);
            int idx = u.prep.off[d] + pos;
            g_csr_src[idx] = s;
            g_csr_w[idx] = u.prep.dinv[s] * u.prep.dinv[d];
        }

        // weight folding: w2'[co,c1,kt] = sum_c2 w2[co,c2,kt]*gcn_w[c1,c2]
        #pragma unroll 1
        for (int i = tid; i < 32 * 3 * 32; i += 256) {
            int co = i & 31;
            int r  = i >> 5;        // r = c1*3 + kt
            int kt = r % 3;
            int c1 = r / 3;
            float s = 0.0f;
            #pragma unroll 8
            for (int c2 = 0; c2 < 32; c2++)
                s += w2[(co * 32 + c2) * 3 + kt] * gcn_w[c1 * 32 + c2];
            g_w2p[i] = s;
        }
        if (tid < 96) {
            int co = tid & 31;
            int kt = tid >> 5;
            float s = 0.0f;
            #pragma unroll 8
            for (int c2 = 0; c2 < 32; c2++)
                s += w2[(co * 32 + c2) * 3 + kt] * gcn_b[c2];
            g_bk[kt * 32 + co] = s;
        }
        return;
    }

    // ---------------- conv1 + relu (2 t's per block) ----------------
    for (int i = tid; i < 96 * 32; i += 256) {
        int co = i & 31;
        int r = i >> 5;
        int kt = r % 3;
        int ci = r / 3;
        w1d[i] = dup2(w1[(co * C_ + ci) * 3 + kt]);
    }
    if (tid < 32) b1d[tid] = dup2(b1[tid]);
    __syncthreads();

    int cog = tid & 7;               // 8 channel groups of 4
    int ptg = tid >> 3;              // 0..31, 4 points each
    int co0 = cog * 4;
    int n0  = blockIdx.x * PTS;
    int nb  = n0 + ptg * 4;
    bool alive = (nb < N_);
    int t0 = blockIdx.y * 2;
    int b  = blockIdx.z;

    bool pv[4];
    pv[0] = (t0 > 0) && alive;
    pv[1] = alive;
    pv[2] = alive;
    pv[3] = (t0 + 2 < T_) && alive;

    ull acc[2][2][4];
    {
        ull bq[4];
        *(ulonglong2*)&bq[0] = *(const ulonglong2*)&b1d[co0];
        *(ulonglong2*)&bq[2] = *(const ulonglong2*)&b1d[co0 + 2];
        #pragma unroll
        for (int tt = 0; tt < 2; tt++)
            #pragma unroll
            for (int pp = 0; pp < 2; pp++)
                #pragma unroll
                for (int c = 0; c < 4; c++) acc[tt][pp][c] = bq[c];
    }

    const float* xrow = x + ((size_t)(b * C_ * T_) + (t0 - 1)) * N_ + nb;
    #pragma unroll 2
    for (int ci = 0; ci < 32; ci++) {
        const float* xr = xrow + ci * (T_ * N_);
        ulonglong2 in[4];
        #pragma unroll
        for (int j = 0; j < 4; j++) {
            if (pv[j]) in[j] = *(const ulonglong2*)(xr + j * N_);
            else { in[j].x = 0ull; in[j].y = 0ull; }
        }
        #pragma unroll
        for (int kt = 0; kt < 3; kt++) {
            ulonglong2 w01 = *(const ulonglong2*)&w1d[(ci * 3 + kt) * 32 + co0];
            ulonglong2 w23 = *(const ulonglong2*)&w1d[(ci * 3 + kt) * 32 + co0 + 2];
            #pragma unroll
            for (int tt = 0; tt < 2; tt++) {
                int j = tt + kt;
                ffma2(acc[tt][0][0], in[j].x, w01.x);
                ffma2(acc[tt][0][1], in[j].x, w01.y);
                ffma2(acc[tt][0][2], in[j].x, w23.x);
                ffma2(acc[tt][0][3], in[j].x, w23.y);
                ffma2(acc[tt][1][0], in[j].y, w01.x);
                ffma2(acc[tt][1][1], in[j].y, w01.y);
                ffma2(acc[tt][1][2], in[j].y, w23.x);
                ffma2(acc[tt][1][3], in[j].y, w23.y);
            }
        }
    }

    // relu -> repack per point into float4(co0..co0+3) -> STS.128 tiles
    float* xwt = u.pool;
    #pragma unroll
    for (int tt = 0; tt < 2; tt++) {
        #pragma unroll
        for (int p = 0; p < 4; p++) {
            int pp = p >> 1, h = p & 1;
            float2 u0 = unpack2(acc[tt][pp][0]);
            float2 u1 = unpack2(acc[tt][pp][1]);
            float2 u2 = unpack2(acc[tt][pp][2]);
            float2 u3 = unpack2(acc[tt][pp][3]);
            float4 v;
            v.x = fmaxf(h ? u0.y : u0.x, 0.0f);
            v.y = fmaxf(h ? u1.y : u1.x, 0.0f);
            v.z = fmaxf(h ? u2.y : u2.x, 0.0f);
            v.w = fmaxf(h ? u3.y : u3.x, 0.0f);
            *(float4*)&xwt[(tt * PTS + ptg * 4 + p) * XWSTRIDE + co0] = v;
        }
    }
    __syncthreads();

    int g0 = b * T_ + t0;
    int rows = min(PTS, N_ - n0);
    int total = rows * C_;
    float* dst0 = g_xw + ((size_t)g0 * N_ + n0) * C_;
    float* dst1 = g_xw + ((size_t)(g0 + 1) * N_ + n0) * C_;
    for (int i = tid; i < total; i += 256) {
        int r = i >> 5, c = i & 31;
        dst0[i] = xwt[r * XWSTRIDE + c];
        dst1[i] = xwt[(PTS + r) * XWSTRIDE + c];
    }
}

// ---------------------------------------------------------------------------
// K2: GCN aggregation over h; 4 graphs per warp. z = aggH + invdeg*h.
// Writes g_gout transposed [g][c][n].
// ---------------------------------------------------------------------------
__global__ void __launch_bounds__(256) k_agg() {
    __shared__ __align__(16) float sbuf[4 * 256];   // [gg][lane*8+warp]
    int warp = threadIdx.x >> 5;
    int lane = threadIdx.x & 31;
    int n  = blockIdx.x * 8 + warp;
    int g0 = blockIdx.y * 4;

    int s0 = g_off[n];
    int s1 = g_off[n + 1];
    const float* __restrict__ xw0 = g_xw + (size_t)g0 * N_ * C_;
    const size_t GS = (size_t)N_ * C_;

    float acc[4] = {0.f, 0.f, 0.f, 0.f};
    int e = s0;
    for (; e + 1 < s1; e += 2) {
        int   sA = g_csr_src[e];
        int   sB = g_csr_src[e + 1];
        float wA = g_csr_w[e];
        float wB = g_csr_w[e + 1];
        float vA[4], vB[4];
        #pragma unroll
        for (int gg = 0; gg < 4; gg++) vA[gg] = __ldg(&xw0[gg * GS + sA * C_ + lane]);
        #pragma unroll
        for (int gg = 0; gg < 4; gg++) vB[gg] = __ldg(&xw0[gg * GS + sB * C_ + lane]);
        #pragma unroll
        for (int gg = 0; gg < 4; gg++) acc[gg] += wA * vA[gg] + wB * vB[gg];
    }
    if (e < s1) {
        int   sA = g_csr_src[e];
        float wA = g_csr_w[e];
        #pragma unroll
        for (int gg = 0; gg < 4; gg++) acc[gg] += wA * __ldg(&xw0[gg * GS + sA * C_ + lane]);
    }
    float idg = g_invdeg[n];
    #pragma unroll
    for (int gg = 0; gg < 4; gg++) {
        acc[gg] += idg * xw0[gg * GS + n * C_ + lane];
        sbuf[gg * 256 + lane * 8 + warp] = acc[gg];
    }
    __syncthreads();

    int n0 = blockIdx.x * 8;
    #pragma unroll
    for (int r = 0; r < 4; r++) {
        int idx = r * 256 + threadIdx.x;
        int gg = idx >> 8;
        int c  = (idx >> 3) & 31;
        int j  = idx & 7;
        g_gout[((size_t)(g0 + gg) * C_ + c) * N_ + n0 + j] = sbuf[gg * 256 + c * 8 + j];
    }
}

// ---------------------------------------------------------------------------
// K3: conv2 with folded weights (pre-dup'd in smem), 2 t's per block,
// point-packed f32x2. Direct coalesced LDG from g_gout [g][c][n];
// per-co float4 STG.128 output. No smem tile.
// ---------------------------------------------------------------------------
__global__ void __launch_bounds__(256, 3) k_conv2(
    const float* __restrict__ b2,
    float* __restrict__ out)
{
    __shared__ __align__(16) ull w2d[96 * 32];   // dup'd folded weights
    __shared__ __align__(16) float bks[3 * 32];
    __shared__ __align__(16) float b2s[32];

    int tid = threadIdx.x;
    for (int i = tid; i < 96 * 32; i += 256) w2d[i] = dup2(g_w2p[i]);
    if (tid < 96) bks[tid] = g_bk[tid];
    if (tid < 32) b2s[tid] = b2[tid];
    __syncthreads();

    int cog = tid & 7;
    int ptg = tid >> 3;
    int co0 = cog * 4;
    int n0  = blockIdx.x * PTS;
    int nb  = n0 + ptg * 4;
    bool alive = (nb < N_);
    int t0 = blockIdx.y * 2;
    int b  = blockIdx.z;

    bool tv0 = (t0 > 0);
    bool tv3 = (t0 + 2 < T_);
    bool pv[4];
    pv[0] = tv0 && alive;
    pv[1] = alive;
    pv[2] = alive;
    pv[3] = tv3 && alive;

    ull acc[2][2][4];
    #pragma unroll
    for (int c = 0; c < 4; c++) {
        int co = co0 + c;
        float bias0 = b2s[co] + bks[32 + co] + (tv0 ? bks[co] : 0.0f) + bks[64 + co];
        float bias1 = b2s[co] + bks[co] + bks[32 + co] + (tv3 ? bks[64 + co] : 0.0f);
        ull b0 = dup2(bias0), b1v = dup2(bias1);
        #pragma unroll
        for (int pp = 0; pp < 2; pp++) {
            acc[0][pp][c] = b0;
            acc[1][pp][c] = b1v;
        }
    }

    // plane j is global t = t0-1+j, channel ci row
    const float* grow = g_gout + ((size_t)(b * T_) + (t0 - 1)) * C_ * N_ + nb;
    #pragma unroll 2
    for (int ci = 0; ci < 32; ci++) {
        const float* gr = grow + (size_t)ci * N_;
        ulonglong2 in[4];
        #pragma unroll
        for (int j = 0; j < 4; j++) {
            if (pv[j]) in[j] = *(const ulonglong2*)(gr + (size_t)j * C_ * N_);
            else { in[j].x = 0ull; in[j].y = 0ull; }
        }
        #pragma unroll
        for (int kt = 0; kt < 3; kt++) {
            ulonglong2 w01 = *(const ulonglong2*)&w2d[(ci * 3 + kt) * 32 + co0];
            ulonglong2 w23 = *(const ulonglong2*)&w2d[(ci * 3 + kt) * 32 + co0 + 2];
            #pragma unroll
            for (int tt = 0; tt < 2; tt++) {
                int j = tt + kt;
                ffma2(acc[tt][0][0], in[j].x, w01.x);
                ffma2(acc[tt][0][1], in[j].x, w01.y);
                ffma2(acc[tt][0][2], in[j].x, w23.x);
                ffma2(acc[tt][0][3], in[j].x, w23.y);
                ffma2(acc[tt][1][0], in[j].y, w01.x);
                ffma2(acc[tt][1][1], in[j].y, w01.y);
                ffma2(acc[tt][1][2], in[j].y, w23.x);
                ffma2(acc[tt][1][3], in[j].y, w23.y);
            }
        }
    }

    if (alive) {
        #pragma unroll
        for (int tt = 0; tt < 2; tt++) {
            #pragma unroll
            for (int c = 0; c < 4; c++) {
                float2 lo = unpack2(acc[tt][0][c]);
                float2 hi = unpack2(acc[tt][1][c]);
                float4 v = make_float4(lo.x, lo.y, hi.x, hi.y);
                int co = co0 + c;
                *(float4*)(out + ((size_t)(b * C_ + co) * T_ + t0 + tt) * N_ + nb) = v;
            }
        }
    }
}

// ---------------------------------------------------------------------------
// Launcher
// ---------------------------------------------------------------------------
extern "C" void kernel_launch(void* const* d_in, const int* in_sizes, int n_in,
                              void* d_out, int out_size) {
    const float* x     = (const float*)d_in[0];
    const void*  edges = d_in[1];
    const float* w1    = (const float*)d_in[2];
    const float* b1    = (const float*)d_in[3];
    const float* gcn_w = (const float*)d_in[4];
    const float* gcn_b = (const float*)d_in[5];
    const float* w2    = (const float*)d_in[6];
    const float* b2    = (const float*)d_in[7];
    float* out = (float*)d_out;

    dim3 g1(NBLK + 1, T_ / 2, B_);   // +1 block does CSR prep + weight folding
    k_conv1<<<g1, 256>>>(x, edges, w1, b1, gcn_w, gcn_b, w2);

    dim3 ga(N_ / 8, BT_ / 4);
    k_agg<<<ga, 256>>>();

    dim3 g2(NBLK, T_ / 2, B_);
    k_conv2<<<g2, 256>>>(b2, out);
}

// round 14
// speedup vs baseline: 1.2392x; 1.2392x over previous
#include <cuda_runtime.h>
#include <math.h>

// Problem constants (fixed shapes)
#define B_  4
#define C_  32
#define T_  48
#define N_  2000
#define E_  16000
#define BT_ (B_ * T_)   // 192

#define PTSB 256        // points per conv block
#define NBLK 8          // ceil(2000/256)
#define HSTRIDE 264     // htile row stride (words)
#define XWSTRIDE 34     // xw transpose tile row stride (words, EVEN for ST.64)

typedef unsigned long long ull;

// ---------------------------------------------------------------------------
// Scratch (device globals)
// ---------------------------------------------------------------------------
__device__ float g_xw[BT_ * N_ * C_];     // [g][n][c] (for gather)
__device__ float g_gout[BT_ * C_ * N_];   // [g][c][n] (for conv2 coalesced reads)
__device__ int   g_srcb[E_];
__device__ int   g_dstb[E_];
__device__ int   g_off[N_ + 1];
__device__ int   g_csr_src[E_];
__device__ float g_csr_w[E_];
__device__ float g_invdeg[N_];

// ---------------------------------------------------------------------------
// f32x2 helpers
// ---------------------------------------------------------------------------
__device__ __forceinline__ ull dup2(float x) {
    ull r;
    unsigned u = __float_as_uint(x);
    asm("mov.b64 %0, {%1, %1};" : "=l"(r) : "r"(u));
    return r;
}
__device__ __forceinline__ void ffma2(ull& acc, ull a, ull b) {
    asm("fma.rn.f32x2 %0, %1, %2, %0;" : "+l"(acc) : "l"(a), "l"(b));
}
__device__ __forceinline__ float2 unpack2(ull v) {
    unsigned lo, hi;
    asm("mov.b64 {%0, %1}, %2;" : "=r"(lo), "=r"(hi) : "l"(v));
    return make_float2(__uint_as_float(lo), __uint_as_float(hi));
}

// ---------------------------------------------------------------------------
// K1: fused conv1+relu+gcn_w GEMM (256 threads, 3 blocks/SM), with CSR
// preprocessing fused in as one extra block (blockIdx.x == NBLK).
// Stage-A K loop is MANUALLY DOUBLE-BUFFERED: ci+1's three plane loads are
// issued before ci's FMA block so L2 latency overlaps compute.
// Thread map: cog = tid&3 (co0 = cog*8), ptg = tid>>2 (4 points each).
// ---------------------------------------------------------------------------
__global__ void __launch_bounds__(256, 3) k_conv1(
    const float* __restrict__ x,
    const void*  __restrict__ edges,
    const float* __restrict__ w1,
    const float* __restrict__ b1,
    const float* __restrict__ gcn_w)
{
    __shared__ __align__(16) union U {
        float pool[8704];                 // htile [32][264] / xwtile [256][34]
        struct {
            int   cnt[2000];
            int   off[2000];
            float dinv[2000];
            int   wsum[8];
            int   is64;
        } prep;
    } u;
    __shared__ __align__(16) float w1s[96 * 32];   // [(ci*3+kt)*32 + co]
    __shared__ __align__(16) float gws[32 * 32];   // [c2*32 + co]
    __shared__ __align__(16) float b1s[32];

    int tid = threadIdx.x;

    // ---------------- fused CSR preprocessing block ----------------
    if (blockIdx.x == NBLK) {
        if (blockIdx.y != 0 || blockIdx.z != 0) return;

        if (tid == 0) {
            const int* q = (const int*)edges;
            int ok = 1;
            #pragma unroll 1
            for (int i = 0; i < 64; i++) {
                if (q[2 * i + 1] != 0) { ok = 0; break; }
            }
            u.prep.is64 = ok;
        }
        for (int i = tid; i < N_; i += 256) u.prep.cnt[i] = 0;
        __syncthreads();
        const int is64 = u.prep.is64;

        #pragma unroll 1
        for (int e = tid; e < E_; e += 256) {
            int s, d;
            if (is64) {
                const long long* p = (const long long*)edges;
                s = (int)p[e];
                d = (int)p[E_ + e];
            } else {
                const int* p = (const int*)edges;
                s = p[e];
                d = p[E_ + e];
            }
            g_srcb[e] = s;
            g_dstb[e] = d;
            atomicAdd(&u.prep.cnt[d], 1);
        }
        __syncthreads();

        // block scan over 2000 counts (8 per thread, 256 threads)
        int lane = tid & 31, wid = tid >> 5;
        int base = tid * 8;
        int c[8];
        int sum = 0;
        #pragma unroll
        for (int i = 0; i < 8; i++) {
            int idx = base + i;
            c[i] = (idx < N_) ? u.prep.cnt[idx] : 0;
            sum += c[i];
        }
        int incl = sum;
        #pragma unroll
        for (int o = 1; o < 32; o <<= 1) {
            int v = __shfl_up_sync(0xffffffffu, incl, o);
            if (lane >= o) incl += v;
        }
        if (lane == 31) u.prep.wsum[wid] = incl;
        __syncthreads();
        int woff = 0;
        #pragma unroll
        for (int w = 0; w < 8; w++) woff += (w < wid) ? u.prep.wsum[w] : 0;
        int run = woff + incl - sum;
        #pragma unroll
        for (int i = 0; i < 8; i++) {
            int idx = base + i;
            if (idx < N_) {
                u.prep.off[idx] = run;
                g_off[idx] = run;
                float deg = (float)c[i] + 1.0f;
                u.prep.dinv[idx] = rsqrtf(deg);
                g_invdeg[idx] = 1.0f / deg;
            }
            run += c[i];
        }
        if (tid == 0) g_off[N_] = E_;
        __syncthreads();
        for (int i = tid; i < N_; i += 256) u.prep.cnt[i] = 0;
        __syncthreads();

        #pragma unroll 1
        for (int e = tid; e < E_; e += 256) {
            int s = g_srcb[e];
            int d = g_dstb[e];
            int pos = atomicAdd(&u.prep.cnt[d], 1);
            int idx = u.prep.off[d] + pos;
            g_csr_src[idx] = s;
            g_csr_w[idx] = u.prep.dinv[s] * u.prep.dinv[d];
        }
        return;
    }

    // ---------------- conv1 + gcn_w GEMM ----------------
    for (int i = tid; i < 96 * 32; i += 256) {
        int co = i & 31;
        int r = i >> 5;
        int kt = r % 3;
        int ci = r / 3;
        w1s[i] = w1[(co * C_ + ci) * 3 + kt];
    }
    for (int i = tid; i < 32 * 32; i += 256) gws[i] = gcn_w[i];
    if (tid < 32) b1s[tid] = b1[tid];
    __syncthreads();

    int cog = tid & 3;
    int ptg = tid >> 2;              // 0..63
    int co0 = cog * 8;
    int n0  = blockIdx.x * PTSB;
    int nb  = n0 + ptg * 4;
    bool alive = (nb < N_);
    int t = blockIdx.y;
    int b = blockIdx.z;

    bool v0 = (t - 1 >= 0);
    bool v2 = (t + 1 < T_);
    bool ld[3] = { v0 && alive, alive, v2 && alive };

    ull acc[4][4];
    {
        const ull* bp = (const ull*)b1s;   // pairs (2c, 2c+1)
        #pragma unroll
        for (int cp = 0; cp < 4; cp++) {
            ull bq = bp[co0 / 2 + cp];
            #pragma unroll
            for (int pt = 0; pt < 4; pt++) acc[pt][cp] = bq;
        }
    }

    // Manually double-buffered K loop: cur holds ci's planes, nxt prefetches ci+1.
    const float* xrow = x + ((size_t)(b * C_ * T_) + (t - 1)) * N_ + nb;
    float4 cur[3], nxt[3];
    {
        const float* xr = xrow;   // ci = 0
        #pragma unroll
        for (int kt = 0; kt < 3; kt++)
            cur[kt] = ld[kt] ? *(const float4*)(xr + kt * N_)
                             : make_float4(0.f, 0.f, 0.f, 0.f);
    }
    #pragma unroll 2
    for (int ci = 0; ci < 32; ci++) {
        if (ci + 1 < 32) {
            const float* xn = xrow + (ci + 1) * (T_ * N_);
            #pragma unroll
            for (int kt = 0; kt < 3; kt++)
                nxt[kt] = ld[kt] ? *(const float4*)(xn + kt * N_)
                                 : make_float4(0.f, 0.f, 0.f, 0.f);
        }
        #pragma unroll
        for (int kt = 0; kt < 3; kt++) {
            ull in[4];
            in[0] = dup2(cur[kt].x); in[1] = dup2(cur[kt].y);
            in[2] = dup2(cur[kt].z); in[3] = dup2(cur[kt].w);
            const ulonglong2* wp = (const ulonglong2*)&w1s[(ci * 3 + kt) * 32 + co0];
            ulonglong2 wa = wp[0];
            ulonglong2 wb = wp[1];
            #pragma unroll
            for (int pt = 0; pt < 4; pt++) {
                ffma2(acc[pt][0], in[pt], wa.x);
                ffma2(acc[pt][1], in[pt], wa.y);
                ffma2(acc[pt][2], in[pt], wb.x);
                ffma2(acc[pt][3], in[pt], wb.y);
            }
        }
        #pragma unroll
        for (int kt = 0; kt < 3; kt++) cur[kt] = nxt[kt];
    }

    // relu -> htile [co][pt]
    float* htile = u.pool;
    int pl = ptg * 4;
    #pragma unroll
    for (int pt = 0; pt < 4; pt++) {
        #pragma unroll
        for (int cp = 0; cp < 4; cp++) {
            float2 v = unpack2(acc[pt][cp]);
            htile[(co0 + 2 * cp) * HSTRIDE + pl + pt]     = fmaxf(v.x, 0.0f);
            htile[(co0 + 2 * cp + 1) * HSTRIDE + pl + pt] = fmaxf(v.y, 0.0f);
        }
    }
    __syncthreads();

    // Stage B: xw = h @ gcn_w
    ull xa[4][4];
    #pragma unroll
    for (int pt = 0; pt < 4; pt++)
        #pragma unroll
        for (int cp = 0; cp < 4; cp++) xa[pt][cp] = 0ull;

    #pragma unroll 4
    for (int c2 = 0; c2 < 32; c2++) {
        float4 hv = *(const float4*)&htile[c2 * HSTRIDE + pl];
        ull in[4];
        in[0] = dup2(hv.x); in[1] = dup2(hv.y);
        in[2] = dup2(hv.z); in[3] = dup2(hv.w);
        const ulonglong2* wp = (const ulonglong2*)&gws[c2 * 32 + co0];
        ulonglong2 wa = wp[0];
        ulonglong2 wb = wp[1];
        #pragma unroll
        for (int pt = 0; pt < 4; pt++) {
            ffma2(xa[pt][0], in[pt], wa.x);
            ffma2(xa[pt][1], in[pt], wa.y);
            ffma2(xa[pt][2], in[pt], wb.x);
            ffma2(xa[pt][3], in[pt], wb.y);
        }
    }
    __syncthreads();   // htile reads done before pool reuse

    // transpose to [pt][co] and store coalesced (XWSTRIDE even -> ST.64 ok)
    float* xwt = u.pool;
    #pragma unroll
    for (int pt = 0; pt < 4; pt++) {
        #pragma unroll
        for (int cp = 0; cp < 4; cp++) {
            float2 v = unpack2(xa[pt][cp]);
            *(float2*)&xwt[(pl + pt) * XWSTRIDE + co0 + 2 * cp] = v;
        }
    }
    __syncthreads();

    int g = b * T_ + t;
    float* dst = g_xw + ((size_t)g * N_ + n0) * C_;
    int rows = min(PTSB, N_ - n0);
    for (int i = tid; i < rows * C_; i += 256) {
        dst[i] = xwt[(i >> 5) * XWSTRIDE + (i & 31)];
    }
}

// ---------------------------------------------------------------------------
// K2: GCN aggregation; 4 graphs per warp (CSR loads amortized, MLP=8).
// Writes g_gout transposed [g][c][n].
// ---------------------------------------------------------------------------
__global__ void __launch_bounds__(256) k_agg(const float* __restrict__ gcn_b) {
    __shared__ __align__(16) float sbuf[4 * 256];   // [gg][lane*8+warp]
    int warp = threadIdx.x >> 5;
    int lane = threadIdx.x & 31;
    int n  = blockIdx.x * 8 + warp;
    int g0 = blockIdx.y * 4;

    int s0 = g_off[n];
    int s1 = g_off[n + 1];
    const float* __restrict__ xw0 = g_xw + (size_t)g0 * N_ * C_;
    const size_t GS = (size_t)N_ * C_;

    float acc[4] = {0.f, 0.f, 0.f, 0.f};
    int e = s0;
    for (; e + 1 < s1; e += 2) {
        int   sA = g_csr_src[e];
        int   sB = g_csr_src[e + 1];
        float wA = g_csr_w[e];
        float wB = g_csr_w[e + 1];
        float vA[4], vB[4];
        #pragma unroll
        for (int gg = 0; gg < 4; gg++) vA[gg] = __ldg(&xw0[gg * GS + sA * C_ + lane]);
        #pragma unroll
        for (int gg = 0; gg < 4; gg++) vB[gg] = __ldg(&xw0[gg * GS + sB * C_ + lane]);
        #pragma unroll
        for (int gg = 0; gg < 4; gg++) acc[gg] += wA * vA[gg] + wB * vB[gg];
    }
    if (e < s1) {
        int   sA = g_csr_src[e];
        float wA = g_csr_w[e];
        #pragma unroll
        for (int gg = 0; gg < 4; gg++) acc[gg] += wA * __ldg(&xw0[gg * GS + sA * C_ + lane]);
    }
    float idg = g_invdeg[n];
    float bia = gcn_b[lane];
    #pragma unroll
    for (int gg = 0; gg < 4; gg++) {
        acc[gg] += idg * xw0[gg * GS + n * C_ + lane] + bia;
        sbuf[gg * 256 + lane * 8 + warp] = acc[gg];
    }
    __syncthreads();

    // transposed store: [g][c][n0..n0+7]
    int n0 = blockIdx.x * 8;
    #pragma unroll
    for (int r = 0; r < 4; r++) {
        int idx = r * 256 + threadIdx.x;
        int gg = idx >> 8;
        int c  = (idx >> 3) & 31;
        int j  = idx & 7;
        g_gout[((size_t)(g0 + gg) * C_ + c) * N_ + n0 + j] = sbuf[gg * 256 + c * 8 + j];
    }
}

// ---------------------------------------------------------------------------
// K3: conv2 (256 threads, 3 blocks/SM); manually double-buffered K loop;
// direct coalesced LDG from g_gout [g][c][n]; per-co float4 STG.128 output.
// ---------------------------------------------------------------------------
__global__ void __launch_bounds__(256, 3) k_conv2(
    const float* __restrict__ w2,
    const float* __restrict__ b2,
    float* __restrict__ out)
{
    __shared__ __align__(16) float w2s[96 * 32];   // [(ci*3+kt)*32 + co]
    __shared__ __align__(16) float b2s[32];

    int tid = threadIdx.x;
    for (int i = tid; i < 96 * 32; i += 256) {
        int co = i & 31;
        int r = i >> 5;
        int kt = r % 3;
        int ci = r / 3;
        w2s[i] = w2[(co * C_ + ci) * 3 + kt];
    }
    if (tid < 32) b2s[tid] = b2[tid];
    __syncthreads();

    int cog = tid & 3;
    int ptg = tid >> 2;
    int co0 = cog * 8;
    int n0  = blockIdx.x * PTSB;
    int nb  = n0 + ptg * 4;
    bool alive = (nb < N_);
    int t = blockIdx.y;
    int b = blockIdx.z;

    bool v0 = (t - 1 >= 0);
    bool v2 = (t + 1 < T_);
    bool ld[3] = { v0 && alive, alive, v2 && alive };

    ull acc[4][4];
    {
        const ull* bp = (const ull*)b2s;
        #pragma unroll
        for (int cp = 0; cp < 4; cp++) {
            ull bq = bp[co0 / 2 + cp];
            #pragma unroll
            for (int pt = 0; pt < 4; pt++) acc[pt][cp] = bq;
        }
    }

    // plane (t-1) for ci = 0; manual double buffer over ci
    const float* gbase = g_gout + ((size_t)(b * T_) + (t - 1)) * C_ * N_ + nb;
    float4 cur[3], nxt[3];
    {
        const float* gr = gbase;   // ci = 0
        #pragma unroll
        for (int kt = 0; kt < 3; kt++)
            cur[kt] = ld[kt] ? *(const float4*)(gr + (size_t)kt * C_ * N_)
                             : make_float4(0.f, 0.f, 0.f, 0.f);
    }
    #pragma unroll 2
    for (int ci = 0; ci < 32; ci++) {
        if (ci + 1 < 32) {
            const float* gn = gbase + (size_t)(ci + 1) * N_;
            #pragma unroll
            for (int kt = 0; kt < 3; kt++)
                nxt[kt] = ld[kt] ? *(const float4*)(gn + (size_t)kt * C_ * N_)
                                 : make_float4(0.f, 0.f, 0.f, 0.f);
        }
        #pragma unroll
        for (int kt = 0; kt < 3; kt++) {
            ull in[4];
            in[0] = dup2(cur[kt].x); in[1] = dup2(cur[kt].y);
            in[2] = dup2(cur[kt].z); in[3] = dup2(cur[kt].w);
            const ulonglong2* wp = (const ulonglong2*)&w2s[(ci * 3 + kt) * 32 + co0];
            ulonglong2 wa = wp[0];
            ulonglong2 wb = wp[1];
            #pragma unroll
            for (int pt = 0; pt < 4; pt++) {
                ffma2(acc[pt][0], in[pt], wa.x);
                ffma2(acc[pt][1], in[pt], wa.y);
                ffma2(acc[pt][2], in[pt], wb.x);
                ffma2(acc[pt][3], in[pt], wb.y);
            }
        }
        #pragma unroll
        for (int kt = 0; kt < 3; kt++) cur[kt] = nxt[kt];
    }

    if (alive) {
        #pragma unroll
        for (int cp = 0; cp < 4; cp++) {
            float2 v0f = unpack2(acc[0][cp]);
            float2 v1f = unpack2(acc[1][cp]);
            float2 v2f = unpack2(acc[2][cp]);
            float2 v3f = unpack2(acc[3][cp]);
            int coA = co0 + 2 * cp;
            int coB = coA + 1;
            float4 lo = make_float4(v0f.x, v1f.x, v2f.x, v3f.x);
            float4 hi = make_float4(v0f.y, v1f.y, v2f.y, v3f.y);
            *(float4*)(out + ((size_t)(b * C_ + coA) * T_ + t) * N_ + nb) = lo;
            *(float4*)(out + ((size_t)(b * C_ + coB) * T_ + t) * N_ + nb) = hi;
        }
    }
}

// ---------------------------------------------------------------------------
// Launcher
// ---------------------------------------------------------------------------
extern "C" void kernel_launch(void* const* d_in, const int* in_sizes, int n_in,
                              void* d_out, int out_size) {
    const float* x     = (const float*)d_in[0];
    const void*  edges = d_in[1];
    const float* w1    = (const float*)d_in[2];
    const float* b1    = (const float*)d_in[3];
    const float* gcn_w = (const float*)d_in[4];
    const float* gcn_b = (const float*)d_in[5];
    const float* w2    = (const float*)d_in[6];
    const float* b2    = (const float*)d_in[7];
    float* out = (float*)d_out;

    dim3 g1(NBLK + 1, T_, B_);       // +1 block does CSR preprocessing
    k_conv1<<<g1, 256>>>(x, edges, w1, b1, gcn_w);

    dim3 ga(N_ / 8, BT_ / 4);
    k_agg<<<ga, 256>>>(gcn_b);

    dim3 g2(NBLK, T_, B_);
    k_conv2<<<g2, 256>>>(w2, b2, out);
}

// round 15
// speedup vs baseline: 1.3178x; 1.0635x over previous
#include <cuda_runtime.h>
#include <math.h>

// Problem constants (fixed shapes)
#define B_  4
#define C_  32
#define T_  48
#define N_  2000
#define E_  16000
#define BT_ (B_ * T_)   // 192

#define PTSB 256        // points per conv block
#define NBLK 8          // ceil(2000/256)
#define XWSTRIDE 34     // transpose tile row stride (words, EVEN for ST.64)

typedef unsigned long long ull;

// ---------------------------------------------------------------------------
// Scratch (device globals)
// ---------------------------------------------------------------------------
__device__ float g_xw[BT_ * N_ * C_];     // h = relu(conv1), layout [g][n][c]
__device__ float g_gout[BT_ * C_ * N_];   // agg output z, layout [g][c][n]
__device__ int   g_srcb[E_];
__device__ int   g_dstb[E_];
__device__ int   g_off[N_ + 1];
__device__ int   g_csr_src[E_];
__device__ float g_csr_w[E_];
__device__ float g_invdeg[N_];
__device__ float g_w2p[32 * 3 * 32];      // folded w2' : [(c1*3+kt)*32 + co]
__device__ float g_bk[3 * 32];            // per-tap bias : [kt*32 + co]

// ---------------------------------------------------------------------------
// f32x2 helpers
// ---------------------------------------------------------------------------
__device__ __forceinline__ ull dup2(float x) {
    ull r;
    unsigned u = __float_as_uint(x);
    asm("mov.b64 %0, {%1, %1};" : "=l"(r) : "r"(u));
    return r;
}
__device__ __forceinline__ ull pack2(float a, float b) {
    ull r;
    asm("mov.b64 %0, {%1, %2};" : "=l"(r)
        : "r"(__float_as_uint(a)), "r"(__float_as_uint(b)));
    return r;
}
__device__ __forceinline__ void ffma2(ull& acc, ull a, ull b) {
    asm("fma.rn.f32x2 %0, %1, %2, %0;" : "+l"(acc) : "l"(a), "l"(b));
}
__device__ __forceinline__ float2 unpack2(ull v) {
    unsigned lo, hi;
    asm("mov.b64 {%0, %1}, %2;" : "=r"(lo), "=r"(hi) : "l"(v));
    return make_float2(__uint_as_float(lo), __uint_as_float(hi));
}

// ---------------------------------------------------------------------------
// K1: conv1+relu, 2 temporal outputs per block sharing 4 x-planes, with
// R10's coalesced thread map (cog=tid&3 -> 8 ptg per warp -> 128B LDG).
// gcn_w folded into conv2 (stage B removed). CSR prep + weight folding
// fused in as one extra block (blockIdx.x == NBLK).
// acc[tt][pt][cp]: f32x2 over channel pair (co0+2cp, co0+2cp+1).
// ---------------------------------------------------------------------------
__global__ void __launch_bounds__(256, 2) k_conv1(
    const float* __restrict__ x,
    const void*  __restrict__ edges,
    const float* __restrict__ w1,
    const float* __restrict__ b1,
    const float* __restrict__ gcn_w,
    const float* __restrict__ gcn_b,
    const float* __restrict__ w2)
{
    __shared__ __align__(16) union U {
        float pool[PTSB * XWSTRIDE];      // one transpose tile [256][34] (8704 w)
        struct {
            int   cnt[2000];
            int   off[2000];
            float dinv[2000];
            int   wsum[8];
            int   is64;
        } prep;
    } u;
    __shared__ __align__(16) float w1s[96 * 32];   // [(ci*3+kt)*32 + co]
    __shared__ __align__(16) float b1s[32];

    int tid = threadIdx.x;

    // ---------------- fused preprocessing block ----------------
    if (blockIdx.x == NBLK) {
        if (blockIdx.y != 0 || blockIdx.z != 0) return;

        if (tid == 0) {
            const int* q = (const int*)edges;
            int ok = 1;
            #pragma unroll 1
            for (int i = 0; i < 64; i++) {
                if (q[2 * i + 1] != 0) { ok = 0; break; }
            }
            u.prep.is64 = ok;
        }
        for (int i = tid; i < N_; i += 256) u.prep.cnt[i] = 0;
        __syncthreads();
        const int is64 = u.prep.is64;

        #pragma unroll 1
        for (int e = tid; e < E_; e += 256) {
            int s, d;
            if (is64) {
                const long long* p = (const long long*)edges;
                s = (int)p[e];
                d = (int)p[E_ + e];
            } else {
                const int* p = (const int*)edges;
                s = p[e];
                d = p[E_ + e];
            }
            g_srcb[e] = s;
            g_dstb[e] = d;
            atomicAdd(&u.prep.cnt[d], 1);
        }
        __syncthreads();

        // block scan over 2000 counts (8 per thread, 256 threads)
        int lane = tid & 31, wid = tid >> 5;
        int base = tid * 8;
        int c[8];
        int sum = 0;
        #pragma unroll
        for (int i = 0; i < 8; i++) {
            int idx = base + i;
            c[i] = (idx < N_) ? u.prep.cnt[idx] : 0;
            sum += c[i];
        }
        int incl = sum;
        #pragma unroll
        for (int o = 1; o < 32; o <<= 1) {
            int v = __shfl_up_sync(0xffffffffu, incl, o);
            if (lane >= o) incl += v;
        }
        if (lane == 31) u.prep.wsum[wid] = incl;
        __syncthreads();
        int woff = 0;
        #pragma unroll
        for (int w = 0; w < 8; w++) woff += (w < wid) ? u.prep.wsum[w] : 0;
        int run = woff + incl - sum;
        #pragma unroll
        for (int i = 0; i < 8; i++) {
            int idx = base + i;
            if (idx < N_) {
                u.prep.off[idx] = run;
                g_off[idx] = run;
                float deg = (float)c[i] + 1.0f;
                u.prep.dinv[idx] = rsqrtf(deg);
                g_invdeg[idx] = 1.0f / deg;
            }
            run += c[i];
        }
        if (tid == 0) g_off[N_] = E_;
        __syncthreads();
        for (int i = tid; i < N_; i += 256) u.prep.cnt[i] = 0;
        __syncthreads();

        #pragma unroll 1
        for (int e = tid; e < E_; e += 256) {
            int s = g_srcb[e];
            int d = g_dstb[e];
            int pos = atomicAdd(&u.prep.cnt[d], 1);
            int idx = u.prep.off[d] + pos;
            g_csr_src[idx] = s;
            g_csr_w[idx] = u.prep.dinv[s] * u.prep.dinv[d];
        }

        // weight folding: w2'[co,c1,kt] = sum_c2 w2[co,c2,kt]*gcn_w[c1,c2]
        #pragma unroll 1
        for (int i = tid; i < 32 * 3 * 32; i += 256) {
            int co = i & 31;
            int r  = i >> 5;        // r = c1*3 + kt
            int kt = r % 3;
            int c1 = r / 3;
            float s = 0.0f;
            #pragma unroll 8
            for (int c2 = 0; c2 < 32; c2++)
                s += w2[(co * 32 + c2) * 3 + kt] * gcn_w[c1 * 32 + c2];
            g_w2p[i] = s;
        }
        // per-tap bias: bk[kt,co] = sum_c2 w2[co,c2,kt]*gcn_b[c2]
        if (tid < 96) {
            int co = tid & 31;
            int kt = tid >> 5;
            float s = 0.0f;
            #pragma unroll 8
            for (int c2 = 0; c2 < 32; c2++)
                s += w2[(co * 32 + c2) * 3 + kt] * gcn_b[c2];
            g_bk[kt * 32 + co] = s;
        }
        return;
    }

    // ---------------- conv1 + relu (2 t's per block) ----------------
    for (int i = tid; i < 96 * 32; i += 256) {
        int co = i & 31;
        int r = i >> 5;
        int kt = r % 3;
        int ci = r / 3;
        w1s[i] = w1[(co * C_ + ci) * 3 + kt];
    }
    if (tid < 32) b1s[tid] = b1[tid];
    __syncthreads();

    int cog = tid & 3;
    int ptg = tid >> 2;              // 0..63, 4 points each (8 per warp -> 128B)
    int co0 = cog * 8;
    int n0  = blockIdx.x * PTSB;
    int nb  = n0 + ptg * 4;
    bool alive = (nb < N_);
    int t0 = blockIdx.y * 2;         // outputs t0, t0+1
    int b  = blockIdx.z;

    // plane validity: planes j=0..3 are global t = t0-1+j
    bool pv0 = (t0 > 0) && alive;
    bool pv1 = alive;
    bool pv3 = (t0 + 2 < T_) && alive;

    ull acc[2][4][4];
    {
        const ull* bp = (const ull*)b1s;   // pairs (2c, 2c+1)
        #pragma unroll
        for (int cp = 0; cp < 4; cp++) {
            ull bq = bp[co0 / 2 + cp];
            #pragma unroll
            for (int tt = 0; tt < 2; tt++)
                #pragma unroll
                for (int pt = 0; pt < 4; pt++) acc[tt][pt][cp] = bq;
        }
    }

    const float* xrow = x + ((size_t)(b * C_ * T_) + (t0 - 1)) * N_ + nb;
    #pragma unroll 2
    for (int ci = 0; ci < 32; ci++) {
        const float* xr = xrow + ci * (T_ * N_);
        float4 in4[4];
        in4[0] = pv0 ? *(const float4*)(xr)           : make_float4(0.f,0.f,0.f,0.f);
        in4[1] = pv1 ? *(const float4*)(xr + N_)      : make_float4(0.f,0.f,0.f,0.f);
        in4[2] = pv1 ? *(const float4*)(xr + 2 * N_)  : make_float4(0.f,0.f,0.f,0.f);
        in4[3] = pv3 ? *(const float4*)(xr + 3 * N_)  : make_float4(0.f,0.f,0.f,0.f);
        #pragma unroll
        for (int kt = 0; kt < 3; kt++) {
            const ulonglong2* wp = (const ulonglong2*)&w1s[(ci * 3 + kt) * 32 + co0];
            ulonglong2 wa = wp[0];
            ulonglong2 wb = wp[1];
            #pragma unroll
            for (int tt = 0; tt < 2; tt++) {
                int j = kt + tt;
                ull i0 = dup2(in4[j].x);
                ull i1 = dup2(in4[j].y);
                ull i2 = dup2(in4[j].z);
                ull i3 = dup2(in4[j].w);
                ffma2(acc[tt][0][0], i0, wa.x);
                ffma2(acc[tt][0][1], i0, wa.y);
                ffma2(acc[tt][0][2], i0, wb.x);
                ffma2(acc[tt][0][3], i0, wb.y);
                ffma2(acc[tt][1][0], i1, wa.x);
                ffma2(acc[tt][1][1], i1, wa.y);
                ffma2(acc[tt][1][2], i1, wb.x);
                ffma2(acc[tt][1][3], i1, wb.y);
                ffma2(acc[tt][2][0], i2, wa.x);
                ffma2(acc[tt][2][1], i2, wa.y);
                ffma2(acc[tt][2][2], i2, wb.x);
                ffma2(acc[tt][2][3], i2, wb.y);
                ffma2(acc[tt][3][0], i3, wa.x);
                ffma2(acc[tt][3][1], i3, wa.y);
                ffma2(acc[tt][3][2], i3, wb.x);
                ffma2(acc[tt][3][3], i3, wb.y);
            }
        }
    }

    // epilogue: per t -> relu -> transpose tile -> coalesced store (tile reused)
    float* xwt = u.pool;
    int pl = ptg * 4;
    int g0 = b * T_ + t0;
    int rows = min(PTSB, N_ - n0);
    int total = rows * C_;
    #pragma unroll
    for (int tt = 0; tt < 2; tt++) {
        #pragma unroll
        for (int pt = 0; pt < 4; pt++) {
            #pragma unroll
            for (int cp = 0; cp < 4; cp++) {
                float2 v = unpack2(acc[tt][pt][cp]);
                v.x = fmaxf(v.x, 0.0f);
                v.y = fmaxf(v.y, 0.0f);
                *(float2*)&xwt[(pl + pt) * XWSTRIDE + co0 + 2 * cp] = v;
            }
        }
        __syncthreads();
        float* dst = g_xw + ((size_t)(g0 + tt) * N_ + n0) * C_;
        for (int i = tid; i < total; i += 256) {
            dst[i] = xwt[(i >> 5) * XWSTRIDE + (i & 31)];
        }
        __syncthreads();
    }
}

// ---------------------------------------------------------------------------
// K2: GCN aggregation over h; 4 graphs per warp. z = aggH + invdeg*h.
// (gcn_w and gcn_b folded into conv2.) Writes g_gout transposed [g][c][n].
// ---------------------------------------------------------------------------
__global__ void __launch_bounds__(256) k_agg() {
    __shared__ __align__(16) float sbuf[4 * 256];   // [gg][lane*8+warp]
    int warp = threadIdx.x >> 5;
    int lane = threadIdx.x & 31;
    int n  = blockIdx.x * 8 + warp;
    int g0 = blockIdx.y * 4;

    int s0 = g_off[n];
    int s1 = g_off[n + 1];
    const float* __restrict__ xw0 = g_xw + (size_t)g0 * N_ * C_;
    const size_t GS = (size_t)N_ * C_;

    float acc[4] = {0.f, 0.f, 0.f, 0.f};
    int e = s0;
    for (; e + 1 < s1; e += 2) {
        int   sA = g_csr_src[e];
        int   sB = g_csr_src[e + 1];
        float wA = g_csr_w[e];
        float wB = g_csr_w[e + 1];
        float vA[4], vB[4];
        #pragma unroll
        for (int gg = 0; gg < 4; gg++) vA[gg] = __ldg(&xw0[gg * GS + sA * C_ + lane]);
        #pragma unroll
        for (int gg = 0; gg < 4; gg++) vB[gg] = __ldg(&xw0[gg * GS + sB * C_ + lane]);
        #pragma unroll
        for (int gg = 0; gg < 4; gg++) acc[gg] += wA * vA[gg] + wB * vB[gg];
    }
    if (e < s1) {
        int   sA = g_csr_src[e];
        float wA = g_csr_w[e];
        #pragma unroll
        for (int gg = 0; gg < 4; gg++) acc[gg] += wA * __ldg(&xw0[gg * GS + sA * C_ + lane]);
    }
    float idg = g_invdeg[n];
    #pragma unroll
    for (int gg = 0; gg < 4; gg++) {
        acc[gg] += idg * xw0[gg * GS + n * C_ + lane];
        sbuf[gg * 256 + lane * 8 + warp] = acc[gg];
    }
    __syncthreads();

    // transposed store: [g][c][n0..n0+7]
    int n0 = blockIdx.x * 8;
    #pragma unroll
    for (int r = 0; r < 4; r++) {
        int idx = r * 256 + threadIdx.x;
        int gg = idx >> 8;
        int c  = (idx >> 3) & 31;
        int j  = idx & 7;
        g_gout[((size_t)(g0 + gg) * C_ + c) * N_ + n0 + j] = sbuf[gg * 256 + c * 8 + j];
    }
}

// ---------------------------------------------------------------------------
// K3: conv2 with folded weights + per-tap bias, 2 temporal outputs per block
// sharing 4 z-planes. Direct coalesced LDG from g_gout [g][c][n]; per-co
// float4 STG.128 output.
// ---------------------------------------------------------------------------
__global__ void __launch_bounds__(256, 2) k_conv2(
    const float* __restrict__ b2,
    float* __restrict__ out)
{
    __shared__ __align__(16) float w2s[96 * 32];   // folded, [(c1*3+kt)*32 + co]
    __shared__ __align__(16) float bks[3 * 32];    // [kt*32 + co]
    __shared__ __align__(16) float b2s[32];

    int tid = threadIdx.x;
    for (int i = tid; i < 96 * 32; i += 256) w2s[i] = g_w2p[i];
    if (tid < 96) bks[tid] = g_bk[tid];
    if (tid < 32) b2s[tid] = b2[tid];
    __syncthreads();

    int cog = tid & 3;
    int ptg = tid >> 2;
    int co0 = cog * 8;
    int n0  = blockIdx.x * PTSB;
    int nb  = n0 + ptg * 4;
    bool alive = (nb < N_);
    int t0 = blockIdx.y * 2;
    int b  = blockIdx.z;

    bool tv0 = (t0 > 0);
    bool tv3 = (t0 + 2 < T_);
    bool pv0 = tv0 && alive;
    bool pv1 = alive;
    bool pv3 = tv3 && alive;

    ull acc[2][4][4];
    #pragma unroll
    for (int cp = 0; cp < 4; cp++) {
        int coA = co0 + 2 * cp;
        int coB = coA + 1;
        // t = t0: taps kt=1,2 always valid; kt=0 iff t0>0
        float b0A = b2s[coA] + bks[32 + coA] + bks[64 + coA] + (tv0 ? bks[coA] : 0.0f);
        float b0B = b2s[coB] + bks[32 + coB] + bks[64 + coB] + (tv0 ? bks[coB] : 0.0f);
        // t = t0+1: taps kt=0,1 always valid; kt=2 iff t0+2<T
        float b1A = b2s[coA] + bks[coA] + bks[32 + coA] + (tv3 ? bks[64 + coA] : 0.0f);
        float b1B = b2s[coB] + bks[coB] + bks[32 + coB] + (tv3 ? bks[64 + coB] : 0.0f);
        ull q0 = pack2(b0A, b0B);
        ull q1 = pack2(b1A, b1B);
        #pragma unroll
        for (int pt = 0; pt < 4; pt++) {
            acc[0][pt][cp] = q0;
            acc[1][pt][cp] = q1;
        }
    }

    // plane j is global t = t0-1+j; row ci within plane
    const float* grow = g_gout + ((size_t)(b * T_) + (t0 - 1)) * C_ * N_ + nb;
    #pragma unroll 2
    for (int ci = 0; ci < 32; ci++) {
        const float* gr = grow + (size_t)ci * N_;
        float4 in4[4];
        in4[0] = pv0 ? *(const float4*)(gr)                        : make_float4(0.f,0.f,0.f,0.f);
        in4[1] = pv1 ? *(const float4*)(gr + (size_t)C_ * N_)      : make_float4(0.f,0.f,0.f,0.f);
        in4[2] = pv1 ? *(const float4*)(gr + (size_t)2 * C_ * N_)  : make_float4(0.f,0.f,0.f,0.f);
        in4[3] = pv3 ? *(const float4*)(gr + (size_t)3 * C_ * N_)  : make_float4(0.f,0.f,0.f,0.f);
        #pragma unroll
        for (int kt = 0; kt < 3; kt++) {
            const ulonglong2* wp = (const ulonglong2*)&w2s[(ci * 3 + kt) * 32 + co0];
            ulonglong2 wa = wp[0];
            ulonglong2 wb = wp[1];
            #pragma unroll
            for (int tt = 0; tt < 2; tt++) {
                int j = kt + tt;
                ull i0 = dup2(in4[j].x);
                ull i1 = dup2(in4[j].y);
                ull i2 = dup2(in4[j].z);
                ull i3 = dup2(in4[j].w);
                ffma2(acc[tt][0][0], i0, wa.x);
                ffma2(acc[tt][0][1], i0, wa.y);
                ffma2(acc[tt][0][2], i0, wb.x);
                ffma2(acc[tt][0][3], i0, wb.y);
                ffma2(acc[tt][1][0], i1, wa.x);
                ffma2(acc[tt][1][1], i1, wa.y);
                ffma2(acc[tt][1][2], i1, wb.x);
                ffma2(acc[tt][1][3], i1, wb.y);
                ffma2(acc[tt][2][0], i2, wa.x);
                ffma2(acc[tt][2][1], i2, wa.y);
                ffma2(acc[tt][2][2], i2, wb.x);
                ffma2(acc[tt][2][3], i2, wb.y);
                ffma2(acc[tt][3][0], i3, wa.x);
                ffma2(acc[tt][3][1], i3, wa.y);
                ffma2(acc[tt][3][2], i3, wb.x);
                ffma2(acc[tt][3][3], i3, wb.y);
            }
        }
    }

    if (alive) {
        #pragma unroll
        for (int tt = 0; tt < 2; tt++) {
            #pragma unroll
            for (int cp = 0; cp < 4; cp++) {
                float2 v0f = unpack2(acc[tt][0][cp]);
                float2 v1f = unpack2(acc[tt][1][cp]);
                float2 v2f = unpack2(acc[tt][2][cp]);
                float2 v3f = unpack2(acc[tt][3][cp]);
                int coA = co0 + 2 * cp;
                int coB = coA + 1;
                float4 lo = make_float4(v0f.x, v1f.x, v2f.x, v3f.x);
                float4 hi = make_float4(v0f.y, v1f.y, v2f.y, v3f.y);
                *(float4*)(out + ((size_t)(b * C_ + coA) * T_ + t0 + tt) * N_ + nb) = lo;
                *(float4*)(out + ((size_t)(b * C_ + coB) * T_ + t0 + tt) * N_ + nb) = hi;
            }
        }
    }
}

// ---------------------------------------------------------------------------
// Launcher
// ---------------------------------------------------------------------------
extern "C" void kernel_launch(void* const* d_in, const int* in_sizes, int n_in,
                              void* d_out, int out_size) {
    const float* x     = (const float*)d_in[0];
    const void*  edges = d_in[1];
    const float* w1    = (const float*)d_in[2];
    const float* b1    = (const float*)d_in[3];
    const float* gcn_w = (const float*)d_in[4];
    const float* gcn_b = (const float*)d_in[5];
    const float* w2    = (const float*)d_in[6];
    const float* b2    = (const float*)d_in[7];
    float* out = (float*)d_out;

    dim3 g1(NBLK + 1, T_ / 2, B_);   // +1 block does CSR prep + weight folding
    k_conv1<<<g1, 256>>>(x, edges, w1, b1, gcn_w, gcn_b, w2);

    dim3 ga(N_ / 8, BT_ / 4);
    k_agg<<<ga, 256>>>();

    dim3 g2(NBLK, T_ / 2, B_);
    k_conv2<<<g2, 256>>>(b2, out);
}

// round 16
// speedup vs baseline: 1.3196x; 1.0014x over previous
#include <cuda_runtime.h>
#include <math.h>

// Problem constants (fixed shapes)
#define B_  4
#define C_  32
#define T_  48
#define N_  2000
#define E_  16000
#define BT_ (B_ * T_)   // 192

#define PTSB 256        // points per conv block
#define NBLK 8          // ceil(2000/256)
#define TSTRIDE 18      // transpose tile row stride (words, EVEN for ST.64)
#define CHALF 16        // channels per block (co-split)

typedef unsigned long long ull;

// ---------------------------------------------------------------------------
// Scratch (device globals)
// ---------------------------------------------------------------------------
__device__ float g_xw[BT_ * N_ * C_];     // h = relu(conv1), layout [g][n][c]
__device__ float g_gout[BT_ * C_ * N_];   // agg output z, layout [g][c][n]
__device__ int   g_srcb[E_];
__device__ int   g_dstb[E_];
__device__ int   g_off[N_ + 1];
__device__ int   g_csr_src[E_];
__device__ float g_csr_w[E_];
__device__ float g_invdeg[N_];
__device__ float g_w2p[32 * 3 * 32];      // folded w2' : [(c1*3+kt)*32 + co]
__device__ float g_bk[3 * 32];            // per-tap bias : [kt*32 + co]

// ---------------------------------------------------------------------------
// f32x2 helpers
// ---------------------------------------------------------------------------
__device__ __forceinline__ ull dup2(float x) {
    ull r;
    unsigned u = __float_as_uint(x);
    asm("mov.b64 %0, {%1, %1};" : "=l"(r) : "r"(u));
    return r;
}
__device__ __forceinline__ ull pack2(float a, float b) {
    ull r;
    asm("mov.b64 %0, {%1, %2};" : "=l"(r)
        : "r"(__float_as_uint(a)), "r"(__float_as_uint(b)));
    return r;
}
__device__ __forceinline__ void ffma2(ull& acc, ull a, ull b) {
    asm("fma.rn.f32x2 %0, %1, %2, %0;" : "+l"(acc) : "l"(a), "l"(b));
}
__device__ __forceinline__ float2 unpack2(ull v) {
    unsigned lo, hi;
    asm("mov.b64 {%0, %1}, %2;" : "=r"(lo), "=r"(hi) : "l"(v));
    return make_float2(__uint_as_float(lo), __uint_as_float(hi));
}

// ---------------------------------------------------------------------------
// K1: conv1+relu, 2 temporal outputs per block, CO-SPLIT: each block does
// 16 of the 32 output channels (halves regs -> 3 blocks/SM -> 24 warps).
// gcn_w folded into conv2. CSR prep + weight folding fused in as one extra
// block (blockIdx.x == 2*NBLK).
// Thread map: cog = tid&3 (lc0 = cog*4), ptg = tid>>2 (4 points, 8/warp
// -> 128B coalesced LDG).
// ---------------------------------------------------------------------------
__global__ void __launch_bounds__(256, 3) k_conv1(
    const float* __restrict__ x,
    const void*  __restrict__ edges,
    const float* __restrict__ w1,
    const float* __restrict__ b1,
    const float* __restrict__ gcn_w,
    const float* __restrict__ gcn_b,
    const float* __restrict__ w2)
{
    __shared__ __align__(16) union U {
        float pool[PTSB * TSTRIDE];       // transpose tile [256][18]
        struct {
            int   cnt[2000];
            int   off[2000];
            float dinv[2000];
            int   wsum[8];
            int   is64;
        } prep;
    } u;
    __shared__ __align__(16) float w1s[96 * CHALF];   // [(ci*3+kt)*16 + lc]
    __shared__ __align__(16) float b1s[CHALF];

    int tid = threadIdx.x;

    // ---------------- fused preprocessing block ----------------
    if (blockIdx.x == 2 * NBLK) {
        if (blockIdx.y != 0 || blockIdx.z != 0) return;

        if (tid == 0) {
            const int* q = (const int*)edges;
            int ok = 1;
            #pragma unroll 1
            for (int i = 0; i < 64; i++) {
                if (q[2 * i + 1] != 0) { ok = 0; break; }
            }
            u.prep.is64 = ok;
        }
        for (int i = tid; i < N_; i += 256) u.prep.cnt[i] = 0;
        __syncthreads();
        const int is64 = u.prep.is64;

        #pragma unroll 1
        for (int e = tid; e < E_; e += 256) {
            int s, d;
            if (is64) {
                const long long* p = (const long long*)edges;
                s = (int)p[e];
                d = (int)p[E_ + e];
            } else {
                const int* p = (const int*)edges;
                s = p[e];
                d = p[E_ + e];
            }
            g_srcb[e] = s;
            g_dstb[e] = d;
            atomicAdd(&u.prep.cnt[d], 1);
        }
        __syncthreads();

        // block scan over 2000 counts (8 per thread, 256 threads)
        int lane = tid & 31, wid = tid >> 5;
        int base = tid * 8;
        int c[8];
        int sum = 0;
        #pragma unroll
        for (int i = 0; i < 8; i++) {
            int idx = base + i;
            c[i] = (idx < N_) ? u.prep.cnt[idx] : 0;
            sum += c[i];
        }
        int incl = sum;
        #pragma unroll
        for (int o = 1; o < 32; o <<= 1) {
            int v = __shfl_up_sync(0xffffffffu, incl, o);
            if (lane >= o) incl += v;
        }
        if (lane == 31) u.prep.wsum[wid] = incl;
        __syncthreads();
        int woff = 0;
        #pragma unroll
        for (int w = 0; w < 8; w++) woff += (w < wid) ? u.prep.wsum[w] : 0;
        int run = woff + incl - sum;
        #pragma unroll
        for (int i = 0; i < 8; i++) {
            int idx = base + i;
            if (idx < N_) {
                u.prep.off[idx] = run;
                g_off[idx] = run;
                float deg = (float)c[i] + 1.0f;
                u.prep.dinv[idx] = rsqrtf(deg);
                g_invdeg[idx] = 1.0f / deg;
            }
            run += c[i];
        }
        if (tid == 0) g_off[N_] = E_;
        __syncthreads();
        for (int i = tid; i < N_; i += 256) u.prep.cnt[i] = 0;
        __syncthreads();

        #pragma unroll 1
        for (int e = tid; e < E_; e += 256) {
            int s = g_srcb[e];
            int d = g_dstb[e];
            int pos = atomicAdd(&u.prep.cnt[d], 1);
            int idx = u.prep.off[d] + pos;
            g_csr_src[idx] = s;
            g_csr_w[idx] = u.prep.dinv[s] * u.prep.dinv[d];
        }

        // weight folding: w2'[co,c1,kt] = sum_c2 w2[co,c2,kt]*gcn_w[c1,c2]
        #pragma unroll 1
        for (int i = tid; i < 32 * 3 * 32; i += 256) {
            int co = i & 31;
            int r  = i >> 5;        // r = c1*3 + kt
            int kt = r % 3;
            int c1 = r / 3;
            float s = 0.0f;
            #pragma unroll 8
            for (int c2 = 0; c2 < 32; c2++)
                s += w2[(co * 32 + c2) * 3 + kt] * gcn_w[c1 * 32 + c2];
            g_w2p[i] = s;
        }
        // per-tap bias: bk[kt,co] = sum_c2 w2[co,c2,kt]*gcn_b[c2]
        if (tid < 96) {
            int co = tid & 31;
            int kt = tid >> 5;
            float s = 0.0f;
            #pragma unroll 8
            for (int c2 = 0; c2 < 32; c2++)
                s += w2[(co * 32 + c2) * 3 + kt] * gcn_b[c2];
            g_bk[kt * 32 + co] = s;
        }
        return;
    }

    // ---------------- conv1 + relu (2 t's, 16 channels per block) ----------
    int ch0 = (blockIdx.x & 1) * CHALF;
    int nbk = blockIdx.x >> 1;

    for (int i = tid; i < 96 * CHALF; i += 256) {
        int lc = i & 15;
        int r = i >> 4;
        int kt = r % 3;
        int ci = r / 3;
        w1s[i] = w1[((ch0 + lc) * C_ + ci) * 3 + kt];
    }
    if (tid < CHALF) b1s[tid] = b1[ch0 + tid];
    __syncthreads();

    int cog = tid & 3;
    int ptg = tid >> 2;              // 0..63, 4 points each (8/warp -> 128B)
    int lc0 = cog * 4;               // local channel base (0,4,8,12)
    int n0  = nbk * PTSB;
    int nb  = n0 + ptg * 4;
    bool alive = (nb < N_);
    int t0 = blockIdx.y * 2;         // outputs t0, t0+1
    int b  = blockIdx.z;

    bool pv0 = (t0 > 0) && alive;
    bool pv1 = alive;
    bool pv3 = (t0 + 2 < T_) && alive;

    ull acc[2][4][2];
    {
        const ull* bp = (const ull*)b1s;
        #pragma unroll
        for (int cp = 0; cp < 2; cp++) {
            ull bq = bp[lc0 / 2 + cp];
            #pragma unroll
            for (int tt = 0; tt < 2; tt++)
                #pragma unroll
                for (int pt = 0; pt < 4; pt++) acc[tt][pt][cp] = bq;
        }
    }

    const float* xrow = x + ((size_t)(b * C_ * T_) + (t0 - 1)) * N_ + nb;
    #pragma unroll 2
    for (int ci = 0; ci < 32; ci++) {
        const float* xr = xrow + ci * (T_ * N_);
        float4 in4[4];
        in4[0] = pv0 ? *(const float4*)(xr)           : make_float4(0.f,0.f,0.f,0.f);
        in4[1] = pv1 ? *(const float4*)(xr + N_)      : make_float4(0.f,0.f,0.f,0.f);
        in4[2] = pv1 ? *(const float4*)(xr + 2 * N_)  : make_float4(0.f,0.f,0.f,0.f);
        in4[3] = pv3 ? *(const float4*)(xr + 3 * N_)  : make_float4(0.f,0.f,0.f,0.f);
        #pragma unroll
        for (int kt = 0; kt < 3; kt++) {
            ulonglong2 w = *(const ulonglong2*)&w1s[(ci * 3 + kt) * CHALF + lc0];
            #pragma unroll
            for (int tt = 0; tt < 2; tt++) {
                int j = kt + tt;
                ull i0 = dup2(in4[j].x);
                ull i1 = dup2(in4[j].y);
                ull i2 = dup2(in4[j].z);
                ull i3 = dup2(in4[j].w);
                ffma2(acc[tt][0][0], i0, w.x);
                ffma2(acc[tt][0][1], i0, w.y);
                ffma2(acc[tt][1][0], i1, w.x);
                ffma2(acc[tt][1][1], i1, w.y);
                ffma2(acc[tt][2][0], i2, w.x);
                ffma2(acc[tt][2][1], i2, w.y);
                ffma2(acc[tt][3][0], i3, w.x);
                ffma2(acc[tt][3][1], i3, w.y);
            }
        }
    }

    // epilogue: per t -> relu -> transpose tile -> coalesced store (tile reused)
    float* xwt = u.pool;
    int pl = ptg * 4;
    int g0 = b * T_ + t0;
    int rows = min(PTSB, N_ - n0);
    int total = rows * CHALF;
    #pragma unroll
    for (int tt = 0; tt < 2; tt++) {
        #pragma unroll
        for (int pt = 0; pt < 4; pt++) {
            #pragma unroll
            for (int cp = 0; cp < 2; cp++) {
                float2 v = unpack2(acc[tt][pt][cp]);
                v.x = fmaxf(v.x, 0.0f);
                v.y = fmaxf(v.y, 0.0f);
                *(float2*)&xwt[(pl + pt) * TSTRIDE + lc0 + 2 * cp] = v;
            }
        }
        __syncthreads();
        float* dst = g_xw + ((size_t)(g0 + tt) * N_ + n0) * C_ + ch0;
        for (int i = tid; i < total; i += 256) {
            int r = i >> 4, c = i & 15;
            dst[r * C_ + c] = xwt[r * TSTRIDE + c];
        }
        __syncthreads();
    }
}

// ---------------------------------------------------------------------------
// K2: GCN aggregation over h; 4 graphs per warp. z = aggH + invdeg*h.
// Writes g_gout transposed [g][c][n].
// ---------------------------------------------------------------------------
__global__ void __launch_bounds__(256) k_agg() {
    __shared__ __align__(16) float sbuf[4 * 256];   // [gg][lane*8+warp]
    int warp = threadIdx.x >> 5;
    int lane = threadIdx.x & 31;
    int n  = blockIdx.x * 8 + warp;
    int g0 = blockIdx.y * 4;

    int s0 = g_off[n];
    int s1 = g_off[n + 1];
    const float* __restrict__ xw0 = g_xw + (size_t)g0 * N_ * C_;
    const size_t GS = (size_t)N_ * C_;

    float acc[4] = {0.f, 0.f, 0.f, 0.f};
    int e = s0;
    for (; e + 1 < s1; e += 2) {
        int   sA = g_csr_src[e];
        int   sB = g_csr_src[e + 1];
        float wA = g_csr_w[e];
        float wB = g_csr_w[e + 1];
        float vA[4], vB[4];
        #pragma unroll
        for (int gg = 0; gg < 4; gg++) vA[gg] = __ldg(&xw0[gg * GS + sA * C_ + lane]);
        #pragma unroll
        for (int gg = 0; gg < 4; gg++) vB[gg] = __ldg(&xw0[gg * GS + sB * C_ + lane]);
        #pragma unroll
        for (int gg = 0; gg < 4; gg++) acc[gg] += wA * vA[gg] + wB * vB[gg];
    }
    if (e < s1) {
        int   sA = g_csr_src[e];
        float wA = g_csr_w[e];
        #pragma unroll
        for (int gg = 0; gg < 4; gg++) acc[gg] += wA * __ldg(&xw0[gg * GS + sA * C_ + lane]);
    }
    float idg = g_invdeg[n];
    #pragma unroll
    for (int gg = 0; gg < 4; gg++) {
        acc[gg] += idg * xw0[gg * GS + n * C_ + lane];
        sbuf[gg * 256 + lane * 8 + warp] = acc[gg];
    }
    __syncthreads();

    // transposed store: [g][c][n0..n0+7]
    int n0 = blockIdx.x * 8;
    #pragma unroll
    for (int r = 0; r < 4; r++) {
        int idx = r * 256 + threadIdx.x;
        int gg = idx >> 8;
        int c  = (idx >> 3) & 31;
        int j  = idx & 7;
        g_gout[((size_t)(g0 + gg) * C_ + c) * N_ + n0 + j] = sbuf[gg * 256 + c * 8 + j];
    }
}

// ---------------------------------------------------------------------------
// K3: conv2 with folded weights + per-tap bias, 2 temporal outputs per block,
// CO-SPLIT (16 channels per block). Direct coalesced LDG from g_gout
// [g][c][n]; per-co float4 STG.128 output.
// ---------------------------------------------------------------------------
__global__ void __launch_bounds__(256, 3) k_conv2(
    const float* __restrict__ b2,
    float* __restrict__ out)
{
    __shared__ __align__(16) float w2s[96 * CHALF];  // [(c1*3+kt)*16 + lc]
    __shared__ __align__(16) float bks[3 * CHALF];   // [kt*16 + lc]
    __shared__ __align__(16) float b2s[CHALF];

    int tid = threadIdx.x;
    int ch0 = (blockIdx.x & 1) * CHALF;
    int nbk = blockIdx.x >> 1;

    for (int i = tid; i < 96 * CHALF; i += 256) {
        int lc = i & 15;
        int r = i >> 4;                 // r = c1*3 + kt
        w2s[i] = g_w2p[r * 32 + ch0 + lc];
    }
    if (tid < 3 * CHALF) {
        int kt = tid >> 4;
        int lc = tid & 15;
        bks[tid] = g_bk[kt * 32 + ch0 + lc];
    }
    if (tid < CHALF) b2s[tid] = b2[ch0 + tid];
    __syncthreads();

    int cog = tid & 3;
    int ptg = tid >> 2;
    int lc0 = cog * 4;
    int n0  = nbk * PTSB;
    int nb  = n0 + ptg * 4;
    bool alive = (nb < N_);
    int t0 = blockIdx.y * 2;
    int b  = blockIdx.z;

    bool tv0 = (t0 > 0);
    bool tv3 = (t0 + 2 < T_);
    bool pv0 = tv0 && alive;
    bool pv1 = alive;
    bool pv3 = tv3 && alive;

    ull acc[2][4][2];
    #pragma unroll
    for (int cp = 0; cp < 2; cp++) {
        int lcA = lc0 + 2 * cp;
        int lcB = lcA + 1;
        // t = t0: taps kt=1,2 always valid; kt=0 iff t0>0
        float b0A = b2s[lcA] + bks[16 + lcA] + bks[32 + lcA] + (tv0 ? bks[lcA] : 0.0f);
        float b0B = b2s[lcB] + bks[16 + lcB] + bks[32 + lcB] + (tv0 ? bks[lcB] : 0.0f);
        // t = t0+1: taps kt=0,1 always valid; kt=2 iff t0+2<T
        float b1A = b2s[lcA] + bks[lcA] + bks[16 + lcA] + (tv3 ? bks[32 + lcA] : 0.0f);
        float b1B = b2s[lcB] + bks[lcB] + bks[16 + lcB] + (tv3 ? bks[32 + lcB] : 0.0f);
        ull q0 = pack2(b0A, b0B);
        ull q1 = pack2(b1A, b1B);
        #pragma unroll
        for (int pt = 0; pt < 4; pt++) {
            acc[0][pt][cp] = q0;
            acc[1][pt][cp] = q1;
        }
    }

    const float* grow = g_gout + ((size_t)(b * T_) + (t0 - 1)) * C_ * N_ + nb;
    #pragma unroll 2
    for (int ci = 0; ci < 32; ci++) {
        const float* gr = grow + (size_t)ci * N_;
        float4 in4[4];
        in4[0] = pv0 ? *(const float4*)(gr)                        : make_float4(0.f,0.f,0.f,0.f);
        in4[1] = pv1 ? *(const float4*)(gr + (size_t)C_ * N_)      : make_float4(0.f,0.f,0.f,0.f);
        in4[2] = pv1 ? *(const float4*)(gr + (size_t)2 * C_ * N_)  : make_float4(0.f,0.f,0.f,0.f);
        in4[3] = pv3 ? *(const float4*)(gr + (size_t)3 * C_ * N_)  : make_float4(0.f,0.f,0.f,0.f);
        #pragma unroll
        for (int kt = 0; kt < 3; kt++) {
            ulonglong2 w = *(const ulonglong2*)&w2s[(ci * 3 + kt) * CHALF + lc0];
            #pragma unroll
            for (int tt = 0; tt < 2; tt++) {
                int j = kt + tt;
                ull i0 = dup2(in4[j].x);
                ull i1 = dup2(in4[j].y);
                ull i2 = dup2(in4[j].z);
                ull i3 = dup2(in4[j].w);
                ffma2(acc[tt][0][0], i0, w.x);
                ffma2(acc[tt][0][1], i0, w.y);
                ffma2(acc[tt][1][0], i1, w.x);
                ffma2(acc[tt][1][1], i1, w.y);
                ffma2(acc[tt][2][0], i2, w.x);
                ffma2(acc[tt][2][1], i2, w.y);
                ffma2(acc[tt][3][0], i3, w.x);
                ffma2(acc[tt][3][1], i3, w.y);
            }
        }
    }

    if (alive) {
        #pragma unroll
        for (int tt = 0; tt < 2; tt++) {
            #pragma unroll
            for (int cp = 0; cp < 2; cp++) {
                float2 v0f = unpack2(acc[tt][0][cp]);
                float2 v1f = unpack2(acc[tt][1][cp]);
                float2 v2f = unpack2(acc[tt][2][cp]);
                float2 v3f = unpack2(acc[tt][3][cp]);
                int coA = ch0 + lc0 + 2 * cp;
                int coB = coA + 1;
                float4 lo = make_float4(v0f.x, v1f.x, v2f.x, v3f.x);
                float4 hi = make_float4(v0f.y, v1f.y, v2f.y, v3f.y);
                *(float4*)(out + ((size_t)(b * C_ + coA) * T_ + t0 + tt) * N_ + nb) = lo;
                *(float4*)(out + ((size_t)(b * C_ + coB) * T_ + t0 + tt) * N_ + nb) = hi;
            }
        }
    }
}

// ---------------------------------------------------------------------------
// Launcher
// ---------------------------------------------------------------------------
extern "C" void kernel_launch(void* const* d_in, const int* in_sizes, int n_in,
                              void* d_out, int out_size) {
    const float* x     = (const float*)d_in[0];
    const void*  edges = d_in[1];
    const float* w1    = (const float*)d_in[2];
    const float* b1    = (const float*)d_in[3];
    const float* gcn_w = (const float*)d_in[4];
    const float* gcn_b = (const float*)d_in[5];
    const float* w2    = (const float*)d_in[6];
    const float* b2    = (const float*)d_in[7];
    float* out = (float*)d_out;

    dim3 g1(2 * NBLK + 1, T_ / 2, B_);   // co-split x2; +1 block = prep+folding
    k_conv1<<<g1, 256>>>(x, edges, w1, b1, gcn_w, gcn_b, w2);

    dim3 ga(N_ / 8, BT_ / 4);
    k_agg<<<ga, 256>>>();

    dim3 g2(2 * NBLK, T_ / 2, B_);       // co-split x2
    k_conv2<<<g2, 256>>>(b2, out);
}